// round 9
// baseline (speedup 1.0000x reference)
#include <cuda_runtime.h>

#define TT  128
#define BSZ 64
#define DD  1024
#define HH  1024
#define NG  4096   // 4*H

typedef unsigned long long u64;

// Scratch (device globals: no allocation allowed in kernel_launch)
__device__ __align__(16) float g_G[(size_t)TT * BSZ * NG];   // x@Wx + b
__device__ __align__(16) float g_c[BSZ * HH];                // cell state

__device__ __forceinline__ u64 fma2(u64 a, u64 b, u64 c) {
    u64 d;
    asm("fma.rn.f32x2 %0, %1, %2, %3;" : "=l"(d) : "l"(a), "l"(b), "l"(c));
    return d;
}
__device__ __forceinline__ u64 pack2(float lo, float hi) {
    u64 d;
    asm("mov.b64 %0, {%1, %2};" : "=l"(d) : "f"(lo), "f"(hi));
    return d;
}
__device__ __forceinline__ void unpack2(u64 v, float& lo, float& hi) {
    asm("mov.b64 {%0, %1}, %2;" : "=f"(lo), "=f"(hi) : "l"(v));
}

// ---------------------------------------------------------------------------
// Phase 1: G[8192,4096] = X @ Wx + b  — round-1 FFMA kernel, VERBATIM (proven).
// ---------------------------------------------------------------------------
__global__ __launch_bounds__(256) void gemm_pre(const float* __restrict__ X,
                                                const float* __restrict__ Wx,
                                                const float* __restrict__ bias) {
    const int N = NG, K = DD;
    __shared__ float As[2][8][128];
    __shared__ float Bs[2][8][128];

    const int tid  = threadIdx.x;
    const int bx   = blockIdx.x;
    const int by   = blockIdx.y;
    const int aRow = tid >> 1;
    const int aK4  = (tid & 1) << 2;
    const int bK   = tid >> 5;
    const int bN4  = (tid & 31) << 2;
    const int tx   = tid & 15;
    const int ty   = tid >> 4;

    const float* Ap = X  + (size_t)(by * 128) * K;
    const float* Bp = Wx + (size_t)(bx * 128);

    float4 aR = *(const float4*)(Ap + (size_t)aRow * K + aK4);
    float4 bR = *(const float4*)(Bp + (size_t)bK * N + bN4);
    As[0][aK4 + 0][aRow] = aR.x;
    As[0][aK4 + 1][aRow] = aR.y;
    As[0][aK4 + 2][aRow] = aR.z;
    As[0][aK4 + 3][aRow] = aR.w;
    *(float4*)&Bs[0][bK][bN4] = bR;
    __syncthreads();

    u64 acc[4][8];
    #pragma unroll
    for (int i = 0; i < 4; ++i)
        #pragma unroll
        for (int j = 0; j < 8; ++j) acc[i][j] = 0ull;

    const int nT = K / 8;
    for (int tk = 0; tk < nT; ++tk) {
        const int cur = tk & 1;
        if (tk + 1 < nT) {
            const int k0 = (tk + 1) * 8;
            aR = *(const float4*)(Ap + (size_t)aRow * K + k0 + aK4);
            bR = *(const float4*)(Bp + (size_t)(k0 + bK) * N + bN4);
        }
        #pragma unroll
        for (int kk = 0; kk < 8; ++kk) {
            const ulonglong2 a01 = *(const ulonglong2*)&As[cur][kk][ty * 8];
            const ulonglong2 a23 = *(const ulonglong2*)&As[cur][kk][ty * 8 + 4];
            u64 ap[4];
            ap[0] = a01.x; ap[1] = a01.y; ap[2] = a23.x; ap[3] = a23.y;
            float br[8];
            *(float4*)&br[0] = *(const float4*)&Bs[cur][kk][tx * 8];
            *(float4*)&br[4] = *(const float4*)&Bs[cur][kk][tx * 8 + 4];
            #pragma unroll
            for (int j = 0; j < 8; ++j) {
                const u64 bb = pack2(br[j], br[j]);
                #pragma unroll
                for (int i = 0; i < 4; ++i)
                    acc[i][j] = fma2(ap[i], bb, acc[i][j]);
            }
        }
        if (tk + 1 < nT) {
            const int nxt = cur ^ 1;
            As[nxt][aK4 + 0][aRow] = aR.x;
            As[nxt][aK4 + 1][aRow] = aR.y;
            As[nxt][aK4 + 2][aRow] = aR.z;
            As[nxt][aK4 + 3][aRow] = aR.w;
            *(float4*)&Bs[nxt][bK][bN4] = bR;
            __syncthreads();
        }
    }

    float* Gp = g_G + (size_t)(by * 128) * N + (size_t)(bx * 128);
    #pragma unroll
    for (int i = 0; i < 4; ++i) {
        #pragma unroll
        for (int j = 0; j < 8; ++j) {
            float lo, hi;
            unpack2(acc[i][j], lo, hi);
            const int col = tx * 8 + j;
            const float bv = bias[bx * 128 + col];
            Gp[(size_t)(ty * 8 + 2 * i)     * N + col] = lo + bv;
            Gp[(size_t)(ty * 8 + 2 * i + 1) * N + col] = hi + bv;
        }
    }
}

// ---------------------------------------------------------------------------
// Phase 2: per-step FFMA kernel, latency-optimized.
// 128 CTAs x 512 thr = 4 k-groups x 128 thr. CTA owns gate-cols
// {gate*1024 + cta*8 + hl} (32 cols), all 64 batch rows. K_s=256, CK=32,
// 8 chunks, double-buffered with register prefetch.
// Thread tile: 4 rows (2 f32x2 pairs) x 4 cols -> 8 fma2 per kk for
// 3 LDS.128 (h pair-quad 16B + w dup 32B).
// smem: ps [4][64][33] f32 @0 (33792B)
//       hT [4][2][32][64] f32 @33792 (65536B)   (transposed h, row-pairs)
//       wD [4][2][32][34] u64 @99328 (69632B)   (pre-duplicated (w,w))
// ---------------------------------------------------------------------------
#define STEP_THREADS 512
#define KG2  4
#define KS2  256
#define CK2  32
#define NCH2 8
#define PS_OFF 0
#define HT_OFF 33792
#define WD_OFF 99328
#define SM2_TOTAL 168960

__global__ __launch_bounds__(STEP_THREADS) void lstm_step2(
    const float* __restrict__ Wh, float* __restrict__ out, int t)
{
    extern __shared__ char sm[];
    float* ps = (float*)(sm + PS_OFF);

    const int tid = threadIdx.x;
    const int cta = blockIdx.x;          // 0..127
    const int kg  = tid >> 7;            // 0..3
    const int v   = tid & 127;
    const int rg  = v >> 3;              // 0..15 -> rows rg*4..rg*4+3
    const int cg  = v & 7;               // 0..7  -> cols cg*4..cg*4+3
    const int r0  = rg * 4;
    const int j0  = cg * 4;

    u64 acc[2][4];
    #pragma unroll
    for (int p = 0; p < 2; ++p)
        #pragma unroll
        for (int j = 0; j < 4; ++j) acc[p][j] = 0ull;

    if (t > 0) {
        const float* hprev = out + (size_t)(t - 1) * BSZ * HH;
        const int kbase = kg * KS2;
        // staging roles within the 128-thread k-group
        const int hRow  = v >> 1;            // 0..63
        const int hK16  = (v & 1) * 16;      // 0 or 16
        const int wKk   = v >> 3;            // 0..15 (also +16)
        const int wCol4 = (v & 7) * 4;       // 0..28
        const int wOff  = (wCol4 >> 3) * HH + cta * 8 + (wCol4 & 7);

        float* hTg = (float*)(sm + HT_OFF) + kg * (2 * 32 * 64);
        u64*   wDg = (u64*)  (sm + WD_OFF) + kg * (2 * 32 * 34);

        const float* hSrc = hprev + (size_t)hRow * HH + kbase + hK16;
        const float* wSrc = Wh + (size_t)(kbase + wKk) * NG + wOff;

        float4 h0, h1, h2, h3, w0, w1;
#define P2L(k0) do {                                            \
    h0 = *(const float4*)(hSrc + (k0));                         \
    h1 = *(const float4*)(hSrc + (k0) + 4);                     \
    h2 = *(const float4*)(hSrc + (k0) + 8);                     \
    h3 = *(const float4*)(hSrc + (k0) + 12);                    \
    w0 = *(const float4*)(wSrc + (size_t)(k0) * NG);            \
    w1 = *(const float4*)(wSrc + (size_t)((k0) + 16) * NG);     \
} while (0)
#define P2S(buf) do {                                           \
    float* hd = hTg + (buf) * (32 * 64);                        \
    float hv[16] = {h0.x, h0.y, h0.z, h0.w, h1.x, h1.y, h1.z, h1.w, \
                    h2.x, h2.y, h2.z, h2.w, h3.x, h3.y, h3.z, h3.w}; \
    _Pragma("unroll")                                           \
    for (int jj = 0; jj < 16; ++jj)                             \
        hd[(hK16 + jj) * 64 + hRow] = hv[jj];                   \
    u64* wd  = wDg + (buf) * (32 * 34) + wKk * 34 + wCol4;      \
    wd[0] = pack2(w0.x, w0.x); wd[1] = pack2(w0.y, w0.y);       \
    wd[2] = pack2(w0.z, w0.z); wd[3] = pack2(w0.w, w0.w);       \
    u64* wd2 = wDg + (buf) * (32 * 34) + (wKk + 16) * 34 + wCol4; \
    wd2[0] = pack2(w1.x, w1.x); wd2[1] = pack2(w1.y, w1.y);     \
    wd2[2] = pack2(w1.z, w1.z); wd2[3] = pack2(w1.w, w1.w);     \
} while (0)

        P2L(0);
        P2S(0);
        __syncthreads();

        for (int ck = 0; ck < NCH2; ++ck) {
            const int buf = ck & 1;
            if (ck + 1 < NCH2) P2L((ck + 1) * CK2);

            const float* hb = hTg + buf * (32 * 64);
            const u64*   wb = wDg + buf * (32 * 34);
            #pragma unroll
            for (int kk = 0; kk < CK2; ++kk) {
                const ulonglong2 hp = *(const ulonglong2*)(hb + kk * 64 + r0);
                const ulonglong2 wA = *(const ulonglong2*)(wb + kk * 34 + j0);
                const ulonglong2 wB = *(const ulonglong2*)(wb + kk * 34 + j0 + 2);
                acc[0][0] = fma2(hp.x, wA.x, acc[0][0]);
                acc[0][1] = fma2(hp.x, wA.y, acc[0][1]);
                acc[0][2] = fma2(hp.x, wB.x, acc[0][2]);
                acc[0][3] = fma2(hp.x, wB.y, acc[0][3]);
                acc[1][0] = fma2(hp.y, wA.x, acc[1][0]);
                acc[1][1] = fma2(hp.y, wA.y, acc[1][1]);
                acc[1][2] = fma2(hp.y, wB.x, acc[1][2]);
                acc[1][3] = fma2(hp.y, wB.y, acc[1][3]);
            }
            if (ck + 1 < NCH2) {
                P2S(buf ^ 1);
                __syncthreads();
            }
        }

        // stash partials: ps[kg][row][col], pad 33
        #pragma unroll
        for (int p = 0; p < 2; ++p) {
            #pragma unroll
            for (int j = 0; j < 4; ++j) {
                float lo, hi;
                unpack2(acc[p][j], lo, hi);
                ps[(kg * 64 + r0 + 2 * p)     * 33 + j0 + j] = lo;
                ps[(kg * 64 + r0 + 2 * p + 1) * 33 + j0 + j] = hi;
            }
        }
    }
    __syncthreads();

    // Epilogue: 512 threads -> 512 outputs (64 rows x 8 h-cols)
    const int row  = tid >> 3;
    const int hl   = tid & 7;
    const int ncol = cta * 8 + hl;
    const float* Grow = g_G + (size_t)t * BSZ * NG + (size_t)row * NG;
    float gi = Grow[ncol];
    float gf = Grow[HH + ncol];
    float gg = Grow[2 * HH + ncol];
    float go = Grow[3 * HH + ncol];
    if (t > 0) {
        #pragma unroll
        for (int g = 0; g < KG2; ++g) {
            const int base = (g * 64 + row) * 33;
            gi += ps[base + hl];
            gf += ps[base + 8 + hl];
            gg += ps[base + 16 + hl];
            go += ps[base + 24 + hl];
        }
    }
    const float iv = __saturatef(gi + 0.5f);
    const float fv = __saturatef(gf + 0.5f);
    const float gv = fminf(fmaxf(gg, -1.0f), 1.0f);
    const float ov = __saturatef(go + 0.5f);
    const float cold = (t > 0) ? g_c[row * HH + ncol] : 0.0f;
    const float cnew = fv * cold + iv * gv;
    const float hnew = ov * fminf(fmaxf(cnew, -1.0f), 1.0f);
    g_c[row * HH + ncol] = cnew;
    out[(size_t)t * BSZ * HH + (size_t)row * HH + ncol] = hnew;
}

// ---------------------------------------------------------------------------
extern "C" void kernel_launch(void* const* d_in, const int* in_sizes, int n_in,
                              void* d_out, int out_size) {
    const float* x  = (const float*)d_in[0];   // [T, B, D]
    const float* Wx = (const float*)d_in[1];   // [D, 4H]
    const float* Wh = (const float*)d_in[2];   // [H, 4H]
    const float* b  = (const float*)d_in[3];   // [4H]
    float* out = (float*)d_out;                // [T, B, H]

    cudaFuncSetAttribute(lstm_step2, cudaFuncAttributeMaxDynamicSharedMemorySize,
                         SM2_TOTAL);

    // Phase 1: precompute G = X @ Wx + b for all timesteps (proven kernel).
    dim3 g1(NG / 128, (TT * BSZ) / 128);       // (32, 64)
    gemm_pre<<<g1, 256>>>(x, Wx, b);

    // Phase 2: 128 sequential fused recurrent steps.
    for (int t = 0; t < TT; ++t) {
        lstm_step2<<<128, STEP_THREADS, SM2_TOTAL>>>(Wh, out, t);
    }
    (void)in_sizes; (void)n_in; (void)out_size;
}

// round 10
// speedup vs baseline: 1.4906x; 1.4906x over previous
#include <cuda_runtime.h>

#define TT  128
#define BSZ 64
#define DD  1024
#define HH  1024
#define NG  4096   // 4*H

typedef unsigned int u32;
typedef unsigned long long u64;

// Scratch (device globals: no allocation allowed in kernel_launch)
__device__ __align__(16) float g_G[(size_t)TT * BSZ * NG];   // x@Wx + b
__device__ __align__(16) float g_c[BSZ * HH];                // cell state

__device__ __forceinline__ u64 fma2(u64 a, u64 b, u64 c) {
    u64 d;
    asm("fma.rn.f32x2 %0, %1, %2, %3;" : "=l"(d) : "l"(a), "l"(b), "l"(c));
    return d;
}
__device__ __forceinline__ u64 pack2(float lo, float hi) {
    u64 d;
    asm("mov.b64 %0, {%1, %2};" : "=l"(d) : "f"(lo), "f"(hi));
    return d;
}
__device__ __forceinline__ void unpack2(u64 v, float& lo, float& hi) {
    asm("mov.b64 {%0, %1}, %2;" : "=f"(lo), "=f"(hi) : "l"(v));
}

// ---------------------------------------------------------------------------
// Phase 1: G[8192,4096] = X @ Wx + b  — round-1 FFMA kernel, VERBATIM (proven,
// runs at ~FFMA peak already).
// ---------------------------------------------------------------------------
__global__ __launch_bounds__(256) void gemm_pre(const float* __restrict__ X,
                                                const float* __restrict__ Wx,
                                                const float* __restrict__ bias) {
    const int N = NG, K = DD;
    __shared__ float As[2][8][128];
    __shared__ float Bs[2][8][128];

    const int tid  = threadIdx.x;
    const int bx   = blockIdx.x;
    const int by   = blockIdx.y;
    const int aRow = tid >> 1;
    const int aK4  = (tid & 1) << 2;
    const int bK   = tid >> 5;
    const int bN4  = (tid & 31) << 2;
    const int tx   = tid & 15;
    const int ty   = tid >> 4;

    const float* Ap = X  + (size_t)(by * 128) * K;
    const float* Bp = Wx + (size_t)(bx * 128);

    float4 aR = *(const float4*)(Ap + (size_t)aRow * K + aK4);
    float4 bR = *(const float4*)(Bp + (size_t)bK * N + bN4);
    As[0][aK4 + 0][aRow] = aR.x;
    As[0][aK4 + 1][aRow] = aR.y;
    As[0][aK4 + 2][aRow] = aR.z;
    As[0][aK4 + 3][aRow] = aR.w;
    *(float4*)&Bs[0][bK][bN4] = bR;
    __syncthreads();

    u64 acc[4][8];
    #pragma unroll
    for (int i = 0; i < 4; ++i)
        #pragma unroll
        for (int j = 0; j < 8; ++j) acc[i][j] = 0ull;

    const int nT = K / 8;
    for (int tk = 0; tk < nT; ++tk) {
        const int cur = tk & 1;
        if (tk + 1 < nT) {
            const int k0 = (tk + 1) * 8;
            aR = *(const float4*)(Ap + (size_t)aRow * K + k0 + aK4);
            bR = *(const float4*)(Bp + (size_t)(k0 + bK) * N + bN4);
        }
        #pragma unroll
        for (int kk = 0; kk < 8; ++kk) {
            const ulonglong2 a01 = *(const ulonglong2*)&As[cur][kk][ty * 8];
            const ulonglong2 a23 = *(const ulonglong2*)&As[cur][kk][ty * 8 + 4];
            u64 ap[4];
            ap[0] = a01.x; ap[1] = a01.y; ap[2] = a23.x; ap[3] = a23.y;
            float br[8];
            *(float4*)&br[0] = *(const float4*)&Bs[cur][kk][tx * 8];
            *(float4*)&br[4] = *(const float4*)&Bs[cur][kk][tx * 8 + 4];
            #pragma unroll
            for (int j = 0; j < 8; ++j) {
                const u64 bb = pack2(br[j], br[j]);
                #pragma unroll
                for (int i = 0; i < 4; ++i)
                    acc[i][j] = fma2(ap[i], bb, acc[i][j]);
            }
        }
        if (tk + 1 < nT) {
            const int nxt = cur ^ 1;
            As[nxt][aK4 + 0][aRow] = aR.x;
            As[nxt][aK4 + 1][aRow] = aR.y;
            As[nxt][aK4 + 2][aRow] = aR.z;
            As[nxt][aK4 + 3][aRow] = aR.w;
            *(float4*)&Bs[nxt][bK][bN4] = bR;
            __syncthreads();
        }
    }

    float* Gp = g_G + (size_t)(by * 128) * N + (size_t)(bx * 128);
    #pragma unroll
    for (int i = 0; i < 4; ++i) {
        #pragma unroll
        for (int j = 0; j < 8; ++j) {
            float lo, hi;
            unpack2(acc[i][j], lo, hi);
            const int col = tx * 8 + j;
            const float bv = bias[bx * 128 + col];
            Gp[(size_t)(ty * 8 + 2 * i)     * N + col] = lo + bv;
            Gp[(size_t)(ty * 8 + 2 * i + 1) * N + col] = hi + bv;
        }
    }
}

// ---------------------------------------------------------------------------
// Phase 2: warp-autonomous step kernel. 128 CTAs x 256 thr = 8 warps.
// CTA owns gate-cols {gate*1024 + cta*8 + j} (32 cols), all 64 rows.
// Warp g = k-group [g*128, g*128+128): stages its own h (transposed row-pair
// u64) and w slices, double-buffered, __syncwarp only. Thread tile 8x8:
// per kk = 2 LDS.128 (h, broadcast) + 2 LDS.128 (w, broadcast) + 8 pack2
// + 32 fma2  ->  ~6 L1 wavefronts per 32 FMA-pipe cycles: FMA-bound.
// smem: ps [8][64][33] f32 @0        (67584 B)
//       hT [8][2][16][64] f32 @67584 (65536 B)  (row-pair u64 layout)
//       wS [8][2][16][32] f32 @133120 (32768 B)
// ---------------------------------------------------------------------------
#define STEP_THREADS 256
#define PS3_OFF 0
#define HT3_OFF 67584
#define WS3_OFF 133120
#define SM3_TOTAL 165888

__global__ __launch_bounds__(STEP_THREADS) void lstm_step3(
    const float* __restrict__ Wh, float* __restrict__ out, int t)
{
    extern __shared__ char sm[];
    float* ps = (float*)(sm + PS3_OFF);

    const int tid  = threadIdx.x;
    const int cta  = blockIdx.x;         // 0..127
    const int g    = tid >> 5;           // warp / k-group 0..7
    const int lane = tid & 31;
    const int rg   = lane & 7;           // row group
    const int cg   = lane >> 3;          // col group == gate
    const int r0   = rg * 8;
    const int j0   = cg * 8;

    u64 acc[4][8];
    #pragma unroll
    for (int i = 0; i < 4; ++i)
        #pragma unroll
        for (int j = 0; j < 8; ++j) acc[i][j] = 0ull;

    if (t > 0) {
        const float* hprev = out + (size_t)(t - 1) * BSZ * HH;
        const int kbase = g * 128;
        float* hTw = (float*)(sm + HT3_OFF) + g * 2048;  // 2 bufs x 1024 f32
        float* wSw = (float*)(sm + WS3_OFF) + g * 1024;  // 2 bufs x 512 f32

        // h staging: lane owns rows 2*lane, 2*lane+1 (16 k per chunk).
        const int hr = lane * 2;
        const float* hSrc0 = hprev + (size_t)hr * HH + kbase;
        const float* hSrc1 = hSrc0 + HH;
        // w staging: lane owns 4 float4 slots: idx = lane*4+i
        int wkk[4], wcol[4];
        size_t wgo[4];
        #pragma unroll
        for (int i = 0; i < 4; ++i) {
            const int idx = lane * 4 + i;
            wkk[i]  = idx >> 3;
            const int q = idx & 7;
            wcol[i] = (q >> 1) * 8 + (q & 1) * 4;
            wgo[i]  = (size_t)(q >> 1) * HH + cta * 8 + (q & 1) * 4;
        }

        float4 ha[4], hc[4], wv[4];
#define P3L(k0) do {                                                        \
    _Pragma("unroll")                                                       \
    for (int i = 0; i < 4; ++i) {                                           \
        ha[i] = *(const float4*)(hSrc0 + (k0) + 4 * i);                     \
        hc[i] = *(const float4*)(hSrc1 + (k0) + 4 * i);                     \
        wv[i] = *(const float4*)(Wh + (size_t)(kbase + (k0) + wkk[i]) * NG  \
                                 + wgo[i]);                                 \
    }                                                                       \
} while (0)
#define P3S(buf) do {                                                       \
    float* hd = hTw + (buf) * 1024;                                         \
    float hva[16], hvb[16];                                                 \
    *(float4*)&hva[0]  = ha[0]; *(float4*)&hva[4]  = ha[1];                 \
    *(float4*)&hva[8]  = ha[2]; *(float4*)&hva[12] = ha[3];                 \
    *(float4*)&hvb[0]  = hc[0]; *(float4*)&hvb[4]  = hc[1];                 \
    *(float4*)&hvb[8]  = hc[2]; *(float4*)&hvb[12] = hc[3];                 \
    _Pragma("unroll")                                                       \
    for (int jj = 0; jj < 16; ++jj)                                         \
        *(u64*)(hd + jj * 64 + hr) = pack2(hva[jj], hvb[jj]);               \
    float* wd_ = wSw + (buf) * 512;                                         \
    _Pragma("unroll")                                                       \
    for (int i = 0; i < 4; ++i)                                             \
        *(float4*)(wd_ + wkk[i] * 32 + wcol[i]) = wv[i];                    \
} while (0)

        P3L(0);
        P3S(0);
        __syncwarp();

        for (int c = 0; c < 8; ++c) {
            const int buf = c & 1;
            if (c + 1 < 8) P3L((c + 1) * 16);

            const float* hb = hTw + buf * 1024;
            const float* wb = wSw + buf * 512;
            #pragma unroll
            for (int kk = 0; kk < 16; ++kk) {
                const ulonglong2 hA = *(const ulonglong2*)(hb + kk * 64 + r0);
                const ulonglong2 hB = *(const ulonglong2*)(hb + kk * 64 + r0 + 4);
                const float4 wq0 = *(const float4*)(wb + kk * 32 + j0);
                const float4 wq1 = *(const float4*)(wb + kk * 32 + j0 + 4);
                u64 hp[4];
                hp[0] = hA.x; hp[1] = hA.y; hp[2] = hB.x; hp[3] = hB.y;
                float wf[8];
                wf[0] = wq0.x; wf[1] = wq0.y; wf[2] = wq0.z; wf[3] = wq0.w;
                wf[4] = wq1.x; wf[5] = wq1.y; wf[6] = wq1.z; wf[7] = wq1.w;
                #pragma unroll
                for (int j = 0; j < 8; ++j) {
                    const u64 wd = pack2(wf[j], wf[j]);
                    #pragma unroll
                    for (int i = 0; i < 4; ++i)
                        acc[i][j] = fma2(hp[i], wd, acc[i][j]);
                }
            }
            if (c + 1 < 8) {
                P3S(buf ^ 1);
                __syncwarp();
            }
        }

        // stash partials: ps[g][row][col], pad 33
        #pragma unroll
        for (int i = 0; i < 4; ++i) {
            #pragma unroll
            for (int j = 0; j < 8; ++j) {
                float lo, hi;
                unpack2(acc[i][j], lo, hi);
                ps[(g * 64 + r0 + 2 * i)     * 33 + j0 + j] = lo;
                ps[(g * 64 + r0 + 2 * i + 1) * 33 + j0 + j] = hi;
            }
        }
    }
    __syncthreads();

    // Epilogue: 256 threads x 2 passes -> 512 outputs (64 rows x 8 h-cols)
    float* hout = out + (size_t)t * BSZ * HH;
    #pragma unroll
    for (int pass = 0; pass < 2; ++pass) {
        const int p    = tid + pass * 256;
        const int row  = p >> 3;
        const int hl   = p & 7;
        const int ncol = cta * 8 + hl;
        const float* Grow = g_G + (size_t)t * BSZ * NG + (size_t)row * NG;
        float gi = Grow[ncol];
        float gf = Grow[HH + ncol];
        float gg = Grow[2 * HH + ncol];
        float go = Grow[3 * HH + ncol];
        if (t > 0) {
            #pragma unroll
            for (int q = 0; q < 8; ++q) {
                const int base = (q * 64 + row) * 33;
                gi += ps[base + hl];
                gf += ps[base + 8 + hl];
                gg += ps[base + 16 + hl];
                go += ps[base + 24 + hl];
            }
        }
        const float iv = __saturatef(gi + 0.5f);
        const float fv = __saturatef(gf + 0.5f);
        const float gv = fminf(fmaxf(gg, -1.0f), 1.0f);
        const float ov = __saturatef(go + 0.5f);
        const float cold = (t > 0) ? g_c[row * HH + ncol] : 0.0f;
        const float cnew = fv * cold + iv * gv;
        const float hnew = ov * fminf(fmaxf(cnew, -1.0f), 1.0f);
        g_c[row * HH + ncol] = cnew;
        hout[(size_t)row * HH + ncol] = hnew;
    }
}

// ---------------------------------------------------------------------------
extern "C" void kernel_launch(void* const* d_in, const int* in_sizes, int n_in,
                              void* d_out, int out_size) {
    const float* x  = (const float*)d_in[0];   // [T, B, D]
    const float* Wx = (const float*)d_in[1];   // [D, 4H]
    const float* Wh = (const float*)d_in[2];   // [H, 4H]
    const float* b  = (const float*)d_in[3];   // [4H]
    float* out = (float*)d_out;                // [T, B, H]

    cudaFuncSetAttribute(lstm_step3, cudaFuncAttributeMaxDynamicSharedMemorySize,
                         SM3_TOTAL);

    // Phase 1: precompute G = X @ Wx + b for all timesteps (proven kernel).
    dim3 g1(NG / 128, (TT * BSZ) / 128);       // (32, 64)
    gemm_pre<<<g1, 256>>>(x, Wx, b);

    // Phase 2: 128 sequential fused recurrent steps.
    for (int t = 0; t < TT; ++t) {
        lstm_step3<<<128, STEP_THREADS, SM3_TOTAL>>>(Wh, out, t);
    }
    (void)in_sizes; (void)n_in; (void)out_size;
}

// round 11
// speedup vs baseline: 2.0841x; 1.3982x over previous
#include <cuda_runtime.h>

#define TT  128
#define BSZ 64
#define DD  1024
#define HH  1024
#define NG  4096   // 4*H

typedef unsigned int u32;
typedef unsigned long long u64;

// Scratch (device globals: no allocation allowed in kernel_launch)
__device__ __align__(16) float g_G[(size_t)TT * BSZ * NG];     // x@Wx + b
__device__ __align__(16) float g_c[BSZ * HH];                  // cell state
__device__ __align__(16) float g_WhP[(size_t)128 * HH * 32];   // gathered Wh slices
__device__ __align__(16) float g_hT[HH * BSZ];                 // h transposed [hcol][row]

__device__ __forceinline__ u64 fma2(u64 a, u64 b, u64 c) {
    u64 d;
    asm("fma.rn.f32x2 %0, %1, %2, %3;" : "=l"(d) : "l"(a), "l"(b), "l"(c));
    return d;
}
__device__ __forceinline__ u64 pack2(float lo, float hi) {
    u64 d;
    asm("mov.b64 %0, {%1, %2};" : "=l"(d) : "f"(lo), "f"(hi));
    return d;
}
__device__ __forceinline__ void unpack2(u64 v, float& lo, float& hi) {
    asm("mov.b64 {%0, %1}, %2;" : "=f"(lo), "=f"(hi) : "l"(v));
}

// ---------------------------------------------------------------------------
// Phase 0: gather Wh into per-CTA contiguous slices.
// g_WhP[c][k][j] = Wh[k][(j>>3)*1024 + c*8 + (j&7)],  j = 0..31.
// grid (128, 8), 256 thr, 4 float4 per thread, coalesced writes.
// ---------------------------------------------------------------------------
__global__ __launch_bounds__(256) void wgather(const float* __restrict__ Wh) {
    const int c  = blockIdx.x;
    const int kb = blockIdx.y;
    const int t  = threadIdx.x;
    float* dst = g_WhP + (size_t)c * (HH * 32);
    #pragma unroll
    for (int i = 0; i < 4; ++i) {
        const int q    = kb * 1024 + i * 256 + t;   // float4 index in slice
        const int base = q * 4;
        const int k    = base >> 5;
        const int j    = base & 31;
        const int gcol = (j >> 3) * HH + c * 8 + (j & 7);
        float4 v = *(const float4*)(Wh + (size_t)k * NG + gcol);
        *(float4*)(dst + base) = v;
    }
}

// ---------------------------------------------------------------------------
// Phase 1: G[8192,4096] = X @ Wx + b  — round-1 FFMA kernel, VERBATIM (proven).
// ---------------------------------------------------------------------------
__global__ __launch_bounds__(256) void gemm_pre(const float* __restrict__ X,
                                                const float* __restrict__ Wx,
                                                const float* __restrict__ bias) {
    const int N = NG, K = DD;
    __shared__ float As[2][8][128];
    __shared__ float Bs[2][8][128];

    const int tid  = threadIdx.x;
    const int bx   = blockIdx.x;
    const int by   = blockIdx.y;
    const int aRow = tid >> 1;
    const int aK4  = (tid & 1) << 2;
    const int bK   = tid >> 5;
    const int bN4  = (tid & 31) << 2;
    const int tx   = tid & 15;
    const int ty   = tid >> 4;

    const float* Ap = X  + (size_t)(by * 128) * K;
    const float* Bp = Wx + (size_t)(bx * 128);

    float4 aR = *(const float4*)(Ap + (size_t)aRow * K + aK4);
    float4 bR = *(const float4*)(Bp + (size_t)bK * N + bN4);
    As[0][aK4 + 0][aRow] = aR.x;
    As[0][aK4 + 1][aRow] = aR.y;
    As[0][aK4 + 2][aRow] = aR.z;
    As[0][aK4 + 3][aRow] = aR.w;
    *(float4*)&Bs[0][bK][bN4] = bR;
    __syncthreads();

    u64 acc[4][8];
    #pragma unroll
    for (int i = 0; i < 4; ++i)
        #pragma unroll
        for (int j = 0; j < 8; ++j) acc[i][j] = 0ull;

    const int nT = K / 8;
    for (int tk = 0; tk < nT; ++tk) {
        const int cur = tk & 1;
        if (tk + 1 < nT) {
            const int k0 = (tk + 1) * 8;
            aR = *(const float4*)(Ap + (size_t)aRow * K + k0 + aK4);
            bR = *(const float4*)(Bp + (size_t)(k0 + bK) * N + bN4);
        }
        #pragma unroll
        for (int kk = 0; kk < 8; ++kk) {
            const ulonglong2 a01 = *(const ulonglong2*)&As[cur][kk][ty * 8];
            const ulonglong2 a23 = *(const ulonglong2*)&As[cur][kk][ty * 8 + 4];
            u64 ap[4];
            ap[0] = a01.x; ap[1] = a01.y; ap[2] = a23.x; ap[3] = a23.y;
            float br[8];
            *(float4*)&br[0] = *(const float4*)&Bs[cur][kk][tx * 8];
            *(float4*)&br[4] = *(const float4*)&Bs[cur][kk][tx * 8 + 4];
            #pragma unroll
            for (int j = 0; j < 8; ++j) {
                const u64 bb = pack2(br[j], br[j]);
                #pragma unroll
                for (int i = 0; i < 4; ++i)
                    acc[i][j] = fma2(ap[i], bb, acc[i][j]);
            }
        }
        if (tk + 1 < nT) {
            const int nxt = cur ^ 1;
            As[nxt][aK4 + 0][aRow] = aR.x;
            As[nxt][aK4 + 1][aRow] = aR.y;
            As[nxt][aK4 + 2][aRow] = aR.z;
            As[nxt][aK4 + 3][aRow] = aR.w;
            *(float4*)&Bs[nxt][bK][bN4] = bR;
            __syncthreads();
        }
    }

    float* Gp = g_G + (size_t)(by * 128) * N + (size_t)(bx * 128);
    #pragma unroll
    for (int i = 0; i < 4; ++i) {
        #pragma unroll
        for (int j = 0; j < 8; ++j) {
            float lo, hi;
            unpack2(acc[i][j], lo, hi);
            const int col = tx * 8 + j;
            const float bv = bias[bx * 128 + col];
            Gp[(size_t)(ty * 8 + 2 * i)     * N + col] = lo + bv;
            Gp[(size_t)(ty * 8 + 2 * i + 1) * N + col] = hi + bv;
        }
    }
}

// ---------------------------------------------------------------------------
// Phase 2: warp-autonomous step kernel, COALESCED staging.
// 128 CTAs x 256 thr = 8 warps; warp g = k-group [g*128,(g+1)*128).
// h comes from g_hT (transposed [hcol][row]) -> per-chunk 4KB linear memcpy.
// w comes from g_WhP (gathered [k][32]) -> per-chunk 2KB linear memcpy.
// Inner loop / reduction / cell math identical to round 10 (proven).
// smem: ps [8][64][33] f32 @0        (67584 B)
//       hT [8][2][16][64] f32 @67584 (65536 B)
//       wS [8][2][16][32] f32 @133120 (32768 B)
//       hs [8][65] f32 @165888       (2080 B)
// ---------------------------------------------------------------------------
#define STEP_THREADS 256
#define PS3_OFF 0
#define HT3_OFF 67584
#define WS3_OFF 133120
#define HS3_OFF 165888
#define SM3_TOTAL 167968

__global__ __launch_bounds__(STEP_THREADS) void lstm_step4(
    float* __restrict__ out, int t)
{
    extern __shared__ char sm[];
    float* ps = (float*)(sm + PS3_OFF);
    float* hs = (float*)(sm + HS3_OFF);

    const int tid  = threadIdx.x;
    const int cta  = blockIdx.x;         // 0..127
    const int g    = tid >> 5;           // warp / k-group 0..7
    const int lane = tid & 31;
    const int rg   = lane & 7;
    const int cg   = lane >> 3;
    const int r0   = rg * 8;
    const int j0   = cg * 8;

    u64 acc[4][8];
    #pragma unroll
    for (int i = 0; i < 4; ++i)
        #pragma unroll
        for (int j = 0; j < 8; ++j) acc[i][j] = 0ull;

    if (t > 0) {
        const int kbase = g * 128;
        float* hTw = (float*)(sm + HT3_OFF) + g * 2048;  // 2 bufs x 1024 f32
        float* wSw = (float*)(sm + WS3_OFF) + g * 1024;  // 2 bufs x 512 f32

        // coalesced sources: both contiguous per chunk
        const float* hSrc = g_hT + (size_t)kbase * BSZ;           // 128 k x 64
        const float* wSrc = g_WhP + (size_t)cta * (HH * 32) + (size_t)kbase * 32;

        float4 hv[8], wv[4];
#define P4L(ck) do {                                                         \
    const float* hc_ = hSrc + (ck) * (16 * 64);                              \
    const float* wc_ = wSrc + (ck) * (16 * 32);                              \
    _Pragma("unroll")                                                        \
    for (int i = 0; i < 8; ++i)                                              \
        hv[i] = *(const float4*)(hc_ + (lane + 32 * i) * 4);                 \
    _Pragma("unroll")                                                        \
    for (int i = 0; i < 4; ++i)                                              \
        wv[i] = *(const float4*)(wc_ + (lane + 32 * i) * 4);                 \
} while (0)
#define P4S(buf) do {                                                        \
    float* hd_ = hTw + (buf) * 1024;                                         \
    float* wd_ = wSw + (buf) * 512;                                          \
    _Pragma("unroll")                                                        \
    for (int i = 0; i < 8; ++i)                                              \
        *(float4*)(hd_ + (lane + 32 * i) * 4) = hv[i];                       \
    _Pragma("unroll")                                                        \
    for (int i = 0; i < 4; ++i)                                              \
        *(float4*)(wd_ + (lane + 32 * i) * 4) = wv[i];                       \
} while (0)

        P4L(0);
        P4S(0);
        __syncwarp();

        for (int c = 0; c < 8; ++c) {
            const int buf = c & 1;
            if (c + 1 < 8) P4L(c + 1);

            const float* hb = hTw + buf * 1024;
            const float* wb = wSw + buf * 512;
            #pragma unroll
            for (int kk = 0; kk < 16; ++kk) {
                const ulonglong2 hA = *(const ulonglong2*)(hb + kk * 64 + r0);
                const ulonglong2 hB = *(const ulonglong2*)(hb + kk * 64 + r0 + 4);
                const float4 wq0 = *(const float4*)(wb + kk * 32 + j0);
                const float4 wq1 = *(const float4*)(wb + kk * 32 + j0 + 4);
                u64 hp[4];
                hp[0] = hA.x; hp[1] = hA.y; hp[2] = hB.x; hp[3] = hB.y;
                float wf[8];
                wf[0] = wq0.x; wf[1] = wq0.y; wf[2] = wq0.z; wf[3] = wq0.w;
                wf[4] = wq1.x; wf[5] = wq1.y; wf[6] = wq1.z; wf[7] = wq1.w;
                #pragma unroll
                for (int j = 0; j < 8; ++j) {
                    const u64 wd = pack2(wf[j], wf[j]);
                    #pragma unroll
                    for (int i = 0; i < 4; ++i)
                        acc[i][j] = fma2(hp[i], wd, acc[i][j]);
                }
            }
            if (c + 1 < 8) {
                P4S(buf ^ 1);
                __syncwarp();
            }
        }

        // stash partials: ps[g][row][col], pad 33
        #pragma unroll
        for (int i = 0; i < 4; ++i) {
            #pragma unroll
            for (int j = 0; j < 8; ++j) {
                float lo, hi;
                unpack2(acc[i][j], lo, hi);
                ps[(g * 64 + r0 + 2 * i)     * 33 + j0 + j] = lo;
                ps[(g * 64 + r0 + 2 * i + 1) * 33 + j0 + j] = hi;
            }
        }
    }
    __syncthreads();

    // Epilogue: 256 threads x 2 passes -> 512 outputs (64 rows x 8 h-cols)
    float* hout = out + (size_t)t * BSZ * HH;
    #pragma unroll
    for (int pass = 0; pass < 2; ++pass) {
        const int p    = tid + pass * 256;
        const int row  = p >> 3;
        const int hl   = p & 7;
        const int ncol = cta * 8 + hl;
        const float* Grow = g_G + (size_t)t * BSZ * NG + (size_t)row * NG;
        float gi = Grow[ncol];
        float gf = Grow[HH + ncol];
        float gg = Grow[2 * HH + ncol];
        float go = Grow[3 * HH + ncol];
        if (t > 0) {
            #pragma unroll
            for (int q = 0; q < 8; ++q) {
                const int base = (q * 64 + row) * 33;
                gi += ps[base + hl];
                gf += ps[base + 8 + hl];
                gg += ps[base + 16 + hl];
                go += ps[base + 24 + hl];
            }
        }
        const float iv = __saturatef(gi + 0.5f);
        const float fv = __saturatef(gf + 0.5f);
        const float gv = fminf(fmaxf(gg, -1.0f), 1.0f);
        const float ov = __saturatef(go + 0.5f);
        const float cold = (t > 0) ? g_c[row * HH + ncol] : 0.0f;
        const float cnew = fv * cold + iv * gv;
        const float hnew = ov * fminf(fmaxf(cnew, -1.0f), 1.0f);
        g_c[row * HH + ncol] = cnew;
        hout[(size_t)row * HH + ncol] = hnew;
        hs[hl * 65 + row] = hnew;          // bounce for transposed write
    }
    __syncthreads();

    // Coalesced transposed h write for next step: g_hT[hcol][row].
    #pragma unroll
    for (int pass = 0; pass < 2; ++pass) {
        const int q   = tid + pass * 256;
        const int hl  = q >> 6;            // 0..7
        const int row = q & 63;
        g_hT[(size_t)(cta * 8 + hl) * BSZ + row] = hs[hl * 65 + row];
    }
}

// ---------------------------------------------------------------------------
extern "C" void kernel_launch(void* const* d_in, const int* in_sizes, int n_in,
                              void* d_out, int out_size) {
    const float* x  = (const float*)d_in[0];   // [T, B, D]
    const float* Wx = (const float*)d_in[1];   // [D, 4H]
    const float* Wh = (const float*)d_in[2];   // [H, 4H]
    const float* b  = (const float*)d_in[3];   // [4H]
    float* out = (float*)d_out;                // [T, B, H]

    cudaFuncSetAttribute(lstm_step4, cudaFuncAttributeMaxDynamicSharedMemorySize,
                         SM3_TOTAL);

    // Phase 0: one-time gather of Wh into per-CTA contiguous slices.
    dim3 gw(128, 8);
    wgather<<<gw, 256>>>(Wh);

    // Phase 1: precompute G = X @ Wx + b for all timesteps (proven kernel).
    dim3 g1(NG / 128, (TT * BSZ) / 128);       // (32, 64)
    gemm_pre<<<g1, 256>>>(x, Wx, b);

    // Phase 2: 128 sequential fused recurrent steps.
    for (int t = 0; t < TT; ++t) {
        lstm_step4<<<128, STEP_THREADS, SM3_TOTAL>>>(out, t);
    }
    (void)in_sizes; (void)n_in; (void)out_size;
}

// round 12
// speedup vs baseline: 2.1477x; 1.0305x over previous
#include <cuda_runtime.h>

#define TT  128
#define BSZ 64
#define DD  1024
#define HH  1024
#define NG  4096   // 4*H

typedef unsigned int u32;
typedef unsigned long long u64;

// Scratch (device globals: no allocation allowed in kernel_launch)
__device__ __align__(16) float g_G[(size_t)TT * BSZ * NG];     // x@Wx + b
__device__ __align__(16) float g_c[BSZ * HH];                  // cell state
__device__ __align__(16) float g_WhP[(size_t)128 * HH * 32];   // gathered Wh slices
__device__ __align__(16) float g_hT[HH * BSZ];                 // h transposed [hcol][row]

__device__ __forceinline__ u64 fma2(u64 a, u64 b, u64 c) {
    u64 d;
    asm("fma.rn.f32x2 %0, %1, %2, %3;" : "=l"(d) : "l"(a), "l"(b), "l"(c));
    return d;
}
__device__ __forceinline__ u64 pack2(float lo, float hi) {
    u64 d;
    asm("mov.b64 %0, {%1, %2};" : "=l"(d) : "f"(lo), "f"(hi));
    return d;
}
__device__ __forceinline__ void unpack2(u64 v, float& lo, float& hi) {
    asm("mov.b64 {%0, %1}, %2;" : "=f"(lo), "=f"(hi) : "l"(v));
}

// ---------------------------------------------------------------------------
// Phase 0: gather Wh into per-CTA contiguous slices (proven, round 11).
// ---------------------------------------------------------------------------
__global__ __launch_bounds__(256) void wgather(const float* __restrict__ Wh) {
    const int c  = blockIdx.x;
    const int kb = blockIdx.y;
    const int t  = threadIdx.x;
    float* dst = g_WhP + (size_t)c * (HH * 32);
    #pragma unroll
    for (int i = 0; i < 4; ++i) {
        const int q    = kb * 1024 + i * 256 + t;
        const int base = q * 4;
        const int k    = base >> 5;
        const int j    = base & 31;
        const int gcol = (j >> 3) * HH + c * 8 + (j & 7);
        float4 v = *(const float4*)(Wh + (size_t)k * NG + gcol);
        *(float4*)(dst + base) = v;
    }
}

// ---------------------------------------------------------------------------
// Phase 1: G[8192,4096] = X @ Wx + b  — round-1 FFMA kernel, VERBATIM (proven).
// ---------------------------------------------------------------------------
__global__ __launch_bounds__(256) void gemm_pre(const float* __restrict__ X,
                                                const float* __restrict__ Wx,
                                                const float* __restrict__ bias) {
    const int N = NG, K = DD;
    __shared__ float As[2][8][128];
    __shared__ float Bs[2][8][128];

    const int tid  = threadIdx.x;
    const int bx   = blockIdx.x;
    const int by   = blockIdx.y;
    const int aRow = tid >> 1;
    const int aK4  = (tid & 1) << 2;
    const int bK   = tid >> 5;
    const int bN4  = (tid & 31) << 2;
    const int tx   = tid & 15;
    const int ty   = tid >> 4;

    const float* Ap = X  + (size_t)(by * 128) * K;
    const float* Bp = Wx + (size_t)(bx * 128);

    float4 aR = *(const float4*)(Ap + (size_t)aRow * K + aK4);
    float4 bR = *(const float4*)(Bp + (size_t)bK * N + bN4);
    As[0][aK4 + 0][aRow] = aR.x;
    As[0][aK4 + 1][aRow] = aR.y;
    As[0][aK4 + 2][aRow] = aR.z;
    As[0][aK4 + 3][aRow] = aR.w;
    *(float4*)&Bs[0][bK][bN4] = bR;
    __syncthreads();

    u64 acc[4][8];
    #pragma unroll
    for (int i = 0; i < 4; ++i)
        #pragma unroll
        for (int j = 0; j < 8; ++j) acc[i][j] = 0ull;

    const int nT = K / 8;
    for (int tk = 0; tk < nT; ++tk) {
        const int cur = tk & 1;
        if (tk + 1 < nT) {
            const int k0 = (tk + 1) * 8;
            aR = *(const float4*)(Ap + (size_t)aRow * K + k0 + aK4);
            bR = *(const float4*)(Bp + (size_t)(k0 + bK) * N + bN4);
        }
        #pragma unroll
        for (int kk = 0; kk < 8; ++kk) {
            const ulonglong2 a01 = *(const ulonglong2*)&As[cur][kk][ty * 8];
            const ulonglong2 a23 = *(const ulonglong2*)&As[cur][kk][ty * 8 + 4];
            u64 ap[4];
            ap[0] = a01.x; ap[1] = a01.y; ap[2] = a23.x; ap[3] = a23.y;
            float br[8];
            *(float4*)&br[0] = *(const float4*)&Bs[cur][kk][tx * 8];
            *(float4*)&br[4] = *(const float4*)&Bs[cur][kk][tx * 8 + 4];
            #pragma unroll
            for (int j = 0; j < 8; ++j) {
                const u64 bb = pack2(br[j], br[j]);
                #pragma unroll
                for (int i = 0; i < 4; ++i)
                    acc[i][j] = fma2(ap[i], bb, acc[i][j]);
            }
        }
        if (tk + 1 < nT) {
            const int nxt = cur ^ 1;
            As[nxt][aK4 + 0][aRow] = aR.x;
            As[nxt][aK4 + 1][aRow] = aR.y;
            As[nxt][aK4 + 2][aRow] = aR.z;
            As[nxt][aK4 + 3][aRow] = aR.w;
            *(float4*)&Bs[nxt][bK][bN4] = bR;
            __syncthreads();
        }
    }

    float* Gp = g_G + (size_t)(by * 128) * N + (size_t)(bx * 128);
    #pragma unroll
    for (int i = 0; i < 4; ++i) {
        #pragma unroll
        for (int j = 0; j < 8; ++j) {
            float lo, hi;
            unpack2(acc[i][j], lo, hi);
            const int col = tx * 8 + j;
            const float bv = bias[bx * 128 + col];
            Gp[(size_t)(ty * 8 + 2 * i)     * N + col] = lo + bv;
            Gp[(size_t)(ty * 8 + 2 * i + 1) * N + col] = hi + bv;
        }
    }
}

// ---------------------------------------------------------------------------
// Phase 2: warp-autonomous step kernel, 16 warps (4/SMSP).
// 128 CTAs x 512 thr = 8 k-groups x 2 row-half warps. Warp (kg, half):
// rows [half*32, half*32+32), k in [kg*128, kg*128+128), all 32 gate cols.
// Each warp stages its OWN h row-half and its OWN copy of w (duplicated per
// half; L2-cheap) -> zero cross-warp sync in mainloop, __syncwarp only.
// Thread tile 4 rows x 8 cols: per kk = 3 LDS.128 + 8 pack2 + 16 fma2.
// smem: ps [8][64][33] f32 @0         (67584 B)
//       hT [16 warps][2][16][32] f32 @67584  (65536 B)
//       wS [16 warps][2][16][32] f32 @133120 (65536 B)
//       hs [8][65] f32 @198656        (2080 B)   total 200736 B
// ---------------------------------------------------------------------------
#define STEP_THREADS 512
#define PS5_OFF 0
#define HT5_OFF 67584
#define WS5_OFF 133120
#define HS5_OFF 198656
#define SM5_TOTAL 200736

__global__ __launch_bounds__(STEP_THREADS) void lstm_step5(
    float* __restrict__ out, int t)
{
    extern __shared__ char sm[];
    float* ps = (float*)(sm + PS5_OFF);
    float* hs = (float*)(sm + HS5_OFF);

    const int tid  = threadIdx.x;
    const int cta  = blockIdx.x;         // 0..127
    const int w    = tid >> 5;           // warp 0..15
    const int kg   = w >> 1;             // k-group 0..7
    const int half = w & 1;              // row half
    const int lane = tid & 31;
    const int rg   = lane & 7;
    const int cg   = lane >> 3;
    const int r0   = rg * 4;             // local row (within 32-row half)
    const int j0   = cg * 8;

    u64 acc[2][8];
    #pragma unroll
    for (int p = 0; p < 2; ++p)
        #pragma unroll
        for (int j = 0; j < 8; ++j) acc[p][j] = 0ull;

    if (t > 0) {
        const int kbase = kg * 128;
        float* hTw = (float*)(sm + HT5_OFF) + w * 1024;  // 2 bufs x 512 f32
        float* wSw = (float*)(sm + WS5_OFF) + w * 1024;  // 2 bufs x 512 f32

        const float* wSrc = g_WhP + (size_t)cta * (HH * 32) + (size_t)kbase * 32;

        // h: lane's 4 float4: f = lane + 32*i -> kk = f>>3, q = f&7;
        //    global = g_hT[(kbase + ck*16 + kk)*64 + half*32 + q*4]
        float4 hv[4], wv[4];
#define P5L(ck) do {                                                         \
    _Pragma("unroll")                                                        \
    for (int i = 0; i < 4; ++i) {                                            \
        const int f  = lane + 32 * i;                                        \
        const int kk = f >> 3, q = f & 7;                                    \
        hv[i] = *(const float4*)(g_hT + (size_t)(kbase + (ck) * 16 + kk) * 64 \
                                 + half * 32 + q * 4);                       \
        wv[i] = *(const float4*)(wSrc + (ck) * 512 + f * 4);                 \
    }                                                                        \
} while (0)
#define P5S(buf) do {                                                        \
    float* hd_ = hTw + (buf) * 512;                                          \
    float* wd_ = wSw + (buf) * 512;                                          \
    _Pragma("unroll")                                                        \
    for (int i = 0; i < 4; ++i) {                                            \
        const int f = lane + 32 * i;                                         \
        *(float4*)(hd_ + f * 4) = hv[i];                                     \
        *(float4*)(wd_ + f * 4) = wv[i];                                     \
    }                                                                        \
} while (0)

        P5L(0);
        P5S(0);
        __syncwarp();

        for (int c = 0; c < 8; ++c) {
            const int buf = c & 1;
            if (c + 1 < 8) P5L(c + 1);

            const float* hb = hTw + buf * 512;
            const float* wb = wSw + buf * 512;
            #pragma unroll
            for (int kk = 0; kk < 16; ++kk) {
                const ulonglong2 hA = *(const ulonglong2*)(hb + kk * 32 + r0);
                const float4 wq0 = *(const float4*)(wb + kk * 32 + j0);
                const float4 wq1 = *(const float4*)(wb + kk * 32 + j0 + 4);
                float wf[8];
                wf[0] = wq0.x; wf[1] = wq0.y; wf[2] = wq0.z; wf[3] = wq0.w;
                wf[4] = wq1.x; wf[5] = wq1.y; wf[6] = wq1.z; wf[7] = wq1.w;
                #pragma unroll
                for (int j = 0; j < 8; ++j) {
                    const u64 wd = pack2(wf[j], wf[j]);
                    acc[0][j] = fma2(hA.x, wd, acc[0][j]);
                    acc[1][j] = fma2(hA.y, wd, acc[1][j]);
                }
            }
            if (c + 1 < 8) {
                P5S(buf ^ 1);
                __syncwarp();
            }
        }

        // stash partials: ps[kg][half*32 + local_row][col], pad 33
        #pragma unroll
        for (int p = 0; p < 2; ++p) {
            #pragma unroll
            for (int j = 0; j < 8; ++j) {
                float lo, hi;
                unpack2(acc[p][j], lo, hi);
                const int rb = kg * 64 + half * 32 + r0 + 2 * p;
                ps[rb * 33 + j0 + j]       = lo;
                ps[(rb + 1) * 33 + j0 + j] = hi;
            }
        }
    }
    __syncthreads();

    // Epilogue: 512 threads -> 512 outputs (64 rows x 8 h-cols)
    float* hout = out + (size_t)t * BSZ * HH;
    {
        const int p    = tid;
        const int row  = p >> 3;
        const int hl   = p & 7;
        const int ncol = cta * 8 + hl;
        const float* Grow = g_G + (size_t)t * BSZ * NG + (size_t)row * NG;
        float gi = Grow[ncol];
        float gf = Grow[HH + ncol];
        float gg = Grow[2 * HH + ncol];
        float go = Grow[3 * HH + ncol];
        if (t > 0) {
            #pragma unroll
            for (int q = 0; q < 8; ++q) {
                const int base = (q * 64 + row) * 33;
                gi += ps[base + hl];
                gf += ps[base + 8 + hl];
                gg += ps[base + 16 + hl];
                go += ps[base + 24 + hl];
            }
        }
        const float iv = __saturatef(gi + 0.5f);
        const float fv = __saturatef(gf + 0.5f);
        const float gv = fminf(fmaxf(gg, -1.0f), 1.0f);
        const float ov = __saturatef(go + 0.5f);
        const float cold = (t > 0) ? g_c[row * HH + ncol] : 0.0f;
        const float cnew = fv * cold + iv * gv;
        const float hnew = ov * fminf(fmaxf(cnew, -1.0f), 1.0f);
        g_c[row * HH + ncol] = cnew;
        hout[(size_t)row * HH + ncol] = hnew;
        hs[hl * 65 + row] = hnew;          // bounce for transposed write
    }
    __syncthreads();

    // Coalesced transposed h write for next step: g_hT[hcol][row].
    {
        const int q   = tid;
        const int hl  = q >> 6;            // 0..7
        const int row = q & 63;
        g_hT[(size_t)(cta * 8 + hl) * BSZ + row] = hs[hl * 65 + row];
    }
}

// ---------------------------------------------------------------------------
extern "C" void kernel_launch(void* const* d_in, const int* in_sizes, int n_in,
                              void* d_out, int out_size) {
    const float* x  = (const float*)d_in[0];   // [T, B, D]
    const float* Wx = (const float*)d_in[1];   // [D, 4H]
    const float* Wh = (const float*)d_in[2];   // [H, 4H]
    const float* b  = (const float*)d_in[3];   // [4H]
    float* out = (float*)d_out;                // [T, B, H]

    cudaFuncSetAttribute(lstm_step5, cudaFuncAttributeMaxDynamicSharedMemorySize,
                         SM5_TOTAL);

    // Phase 0: one-time gather of Wh into per-CTA contiguous slices.
    dim3 gw(128, 8);
    wgather<<<gw, 256>>>(Wh);

    // Phase 1: precompute G = X @ Wx + b for all timesteps (proven kernel).
    dim3 g1(NG / 128, (TT * BSZ) / 128);       // (32, 64)
    gemm_pre<<<g1, 256>>>(x, Wx, b);

    // Phase 2: 128 sequential fused recurrent steps.
    for (int t = 0; t < TT; ++t) {
        lstm_step5<<<128, STEP_THREADS, SM5_TOTAL>>>(out, t);
    }
    (void)in_sizes; (void)n_in; (void)out_size;
}